// round 8
// baseline (speedup 1.0000x reference)
#include <cuda_runtime.h>
#include <cstddef>

// B=128, D=1024. d_in[0]=mu (131072 f32), d_in[1]=Sigma (128*1024*1024 f32)
// d_out = [mu_out 131072 f32 | Sigma_out 134217728 f32]
//
// Status: at the mixed-stream HBM wall (6.4 TB/s across 6 configs; traffic
// algorithmically minimal: 512 MB compulsory stores + ~253 MB active-row
// loads). This round removes the last non-memory overhead: persistent
// grid-stride blocks (1 wave, 1184 CTAs) instead of 32768 short-lived CTAs,
// keeping the best-known access pattern (4 rows/group, float4, streaming
// hints, zero-row stores issued before loads).

static constexpr int B = 128;
static constexpr int D = 1024;
static constexpr int ROWS = 4;
static constexpr int NGROUPS = (B * D) / ROWS;   // 32768 row-groups
static constexpr int GRID = 148 * 8;             // one full wave at occ 8

__global__ __launch_bounds__(256) void rvrelu_persist_kernel(
    const float4* __restrict__ Sigma,
    const float*  __restrict__ mu,
    float4* __restrict__ Sigma_out,
    float4* __restrict__ mu_out4) {

    const int t = threadIdx.x;                   // 0..255
    const float4 zero = make_float4(0.0f, 0.0f, 0.0f, 0.0f);

    for (int blk = blockIdx.x; blk < NGROUPS; blk += GRID) {
        const int row0 = blk << 2;               // first of 4 rows
        const int b    = row0 >> 10;             // batch index

        // 4 row masks in one aligned 16B load (L2-hot)
        const float4 mi4 = __ldg(reinterpret_cast<const float4*>(mu) + blk);
        const float mis[ROWS] = {mi4.x, mi4.y, mi4.z, mi4.w};

        const size_t base = (size_t)row0 * (D / 4) + t;   // float4 index

        // Phase 0: drain zero rows into the write stream immediately
#pragma unroll
        for (int r = 0; r < ROWS; r++) {
            if (mis[r] <= 0.0f) {
                __stcs(Sigma_out + base + (size_t)r * (D / 4), zero);
            }
        }

        // fused mu_out: one relu'd float4 store per group
        if (t == 0) {
            float4 rr;
            rr.x = mi4.x > 0.0f ? mi4.x : 0.0f;
            rr.y = mi4.y > 0.0f ? mi4.y : 0.0f;
            rr.z = mi4.z > 0.0f ? mi4.z : 0.0f;
            rr.w = mi4.w > 0.0f ? mi4.w : 0.0f;
            __stcs(mu_out4 + blk, rr);
        }

        // column mask: mu[b, 4t..4t+3], shared by all 4 rows (L2-hot)
        const float4 mrow =
            __ldg(reinterpret_cast<const float4*>(mu + (size_t)b * D) + t);

        // Phase 1: front-batch active-row loads (streaming, evict-first)
        float4 v[ROWS];
#pragma unroll
        for (int r = 0; r < ROWS; r++) {
            if (mis[r] > 0.0f) {
                v[r] = __ldcs(Sigma + base + (size_t)r * (D / 4));
            }
        }

        // Phase 2: mask + store active rows
#pragma unroll
        for (int r = 0; r < ROWS; r++) {
            if (mis[r] > 0.0f) {
                float4 o = v[r];
                o.x = mrow.x > 0.0f ? o.x : 0.0f;
                o.y = mrow.y > 0.0f ? o.y : 0.0f;
                o.z = mrow.z > 0.0f ? o.z : 0.0f;
                o.w = mrow.w > 0.0f ? o.w : 0.0f;
                __stcs(Sigma_out + base + (size_t)r * (D / 4), o);
            }
        }
    }
}

extern "C" void kernel_launch(void* const* d_in, const int* in_sizes, int n_in,
                              void* d_out, int out_size) {
    const float* mu    = (const float*)d_in[0];
    const float* Sigma = (const float*)d_in[1];

    float4* mu_out4   = (float4*)d_out;
    float4* Sigma_out = (float4*)((float*)d_out + (size_t)B * D);

    rvrelu_persist_kernel<<<GRID, 256>>>(
        (const float4*)Sigma, mu, Sigma_out, mu_out4);
}

// round 10
// speedup vs baseline: 1.2942x; 1.2942x over previous
#include <cuda_runtime.h>
#include <cstddef>

// B=128, D=1024. d_in[0]=mu (131072 f32), d_in[1]=Sigma (128*1024*1024 f32)
// d_out = [mu_out 131072 f32 | Sigma_out 134217728 f32]
//
// FINAL (R6 config, re-bench for confirmation). At the mixed-stream HBM wall:
// 6 configs (MLP4/8, 16B/32B, default/streaming, store-first, persistent)
// bracket 6.32-6.41 TB/s; persistent-CTA variant regressed to 5.16 TB/s,
// proving CTA-churn supplies the chip-level MLP. Traffic is algorithmically
// minimal: 512 MB compulsory stores + ~253 MB active-row loads (inactive
// rows are written as zeros without reading Sigma).
//
// Layout: one CTA per 4 consecutive Sigma rows (always within one batch b).
// 256 threads; thread t owns columns [4t, 4t+4) of all 4 rows.
//   Phase 0: zero-row stores issued first (independent of any load)
//   Phase 1: front-batched active-row loads (evict-first)
//   Phase 2: column-mask + store
// mu_out fused: thread 0 writes the relu'd 4-row mask vector.

static constexpr int B = 128;
static constexpr int D = 1024;
static constexpr int ROWS = 4;

__global__ __launch_bounds__(256) void rvrelu_final_kernel(
    const float4* __restrict__ Sigma,
    const float*  __restrict__ mu,
    float4* __restrict__ Sigma_out,
    float4* __restrict__ mu_out4) {

    const int blk  = blockIdx.x;        // 0 .. 32767
    const int row0 = blk << 2;          // first of 4 rows
    const int b    = row0 >> 10;        // batch index
    const int t    = threadIdx.x;       // 0..255

    // 4 row masks in one aligned 16B load (L2-hot)
    const float4 mi4 = __ldg(reinterpret_cast<const float4*>(mu) + blk);
    const float mis[ROWS] = {mi4.x, mi4.y, mi4.z, mi4.w};

    const size_t base = (size_t)row0 * (D / 4) + t;   // float4 index
    const float4 zero = make_float4(0.0f, 0.0f, 0.0f, 0.0f);

    // Phase 0: drain zero rows into the write stream immediately
#pragma unroll
    for (int r = 0; r < ROWS; r++) {
        if (mis[r] <= 0.0f) {
            __stcs(Sigma_out + base + (size_t)r * (D / 4), zero);
        }
    }

    // fused mu_out: one relu'd float4 store per block
    if (t == 0) {
        float4 rr;
        rr.x = mi4.x > 0.0f ? mi4.x : 0.0f;
        rr.y = mi4.y > 0.0f ? mi4.y : 0.0f;
        rr.z = mi4.z > 0.0f ? mi4.z : 0.0f;
        rr.w = mi4.w > 0.0f ? mi4.w : 0.0f;
        __stcs(mu_out4 + blk, rr);
    }

    // column mask: mu[b, 4t..4t+3], shared by all 4 rows (L2-hot)
    const float4 mrow =
        __ldg(reinterpret_cast<const float4*>(mu + (size_t)b * D) + t);

    // Phase 1: front-batch all active-row loads (streaming, evict-first)
    float4 v[ROWS];
#pragma unroll
    for (int r = 0; r < ROWS; r++) {
        if (mis[r] > 0.0f) {
            v[r] = __ldcs(Sigma + base + (size_t)r * (D / 4));
        }
    }

    // Phase 2: mask + store active rows
#pragma unroll
    for (int r = 0; r < ROWS; r++) {
        if (mis[r] > 0.0f) {
            float4 o = v[r];
            o.x = mrow.x > 0.0f ? o.x : 0.0f;
            o.y = mrow.y > 0.0f ? o.y : 0.0f;
            o.z = mrow.z > 0.0f ? o.z : 0.0f;
            o.w = mrow.w > 0.0f ? o.w : 0.0f;
            __stcs(Sigma_out + base + (size_t)r * (D / 4), o);
        }
    }
}

extern "C" void kernel_launch(void* const* d_in, const int* in_sizes, int n_in,
                              void* d_out, int out_size) {
    const float* mu    = (const float*)d_in[0];
    const float* Sigma = (const float*)d_in[1];

    float4* mu_out4   = (float4*)d_out;
    float4* Sigma_out = (float4*)((float*)d_out + (size_t)B * D);

    rvrelu_final_kernel<<<(B * D) / ROWS, 256>>>(
        (const float4*)Sigma, mu, Sigma_out, mu_out4);
}